// round 2
// baseline (speedup 1.0000x reference)
#include <cuda_runtime.h>
#include <math.h>

// Problem constants
#define BB   4096
#define NN   64
#define DD   12
#define SSS  5
#define II   7
#define HH   256
#define G4   1024      // 4*H
#define MM1  512
#define MM2  512
#define AA   81

#define TB        16           // batch rows per block (LSTM kernel)
#define NTILES    (BB/TB)      // 256 blocks
#define NTHREADS  256
#define JP        264          // padded joint stride (261 -> 264)

// ---------------- device scratch (static, no allocation) ----------------
static __device__ __align__(16) float g_xs[BB*NN*8];      // sorted features, padded to 8
static __device__ __align__(16) float g_WihT[II*G4];      // [k][j] transposed W_ih
static __device__ __align__(16) float g_WhhT[HH*G4];      // [k][j] transposed W_hh
static __device__ __align__(16) float g_bsum[G4];         // b_ih + b_hh

// ---------------- packed fp32x2 helpers (Blackwell) ----------------
__device__ __forceinline__ unsigned long long packf2(float lo, float hi){
  unsigned long long r;
  asm("mov.b64 %0, {%1, %2};" : "=l"(r) : "f"(lo), "f"(hi));
  return r;
}
__device__ __forceinline__ void unpackf2(unsigned long long v, float& lo, float& hi){
  asm("mov.b64 {%0, %1}, %2;" : "=f"(lo), "=f"(hi) : "l"(v));
}
__device__ __forceinline__ unsigned long long fma2(unsigned long long a, unsigned long long b, unsigned long long c){
  unsigned long long d;
  asm("fma.rn.f32x2 %0, %1, %2, %3;" : "=l"(d) : "l"(a), "l"(b), "l"(c));
  return d;
}

__device__ __forceinline__ float sigf(float x){
  return 1.0f / (1.0f + __expf(-x));
}
__device__ __forceinline__ float tanh_fast(float x){
  float ax = fabsf(x);
  float e  = __expf(-2.0f * ax);
  float t  = (1.0f - e) / (1.0f + e);
  return copysignf(t, x);
}

// ---------------- prep: transpose weights, sum biases ----------------
__global__ void prep_kernel(const float* __restrict__ Wih, const float* __restrict__ Whh,
                            const float* __restrict__ bih, const float* __restrict__ bhh){
  int idx = blockIdx.x * blockDim.x + threadIdx.x;
  int stride = gridDim.x * blockDim.x;
  for (int o = idx; o < HH*G4; o += stride){
    int k = o >> 10, j = o & 1023;
    g_WhhT[o] = Whh[j*HH + k];
  }
  for (int o = idx; o < II*G4; o += stride){
    int k = o >> 10, j = o & 1023;
    g_WihT[o] = Wih[j*II + k];
  }
  for (int o = idx; o < G4; o += stride){
    g_bsum[o] = bih[o] + bhh[o];
  }
}

// ---------------- sort by distance (desc, stable) + gather features ----------------
__global__ void sort_gather_kernel(const float* __restrict__ state){
  int b = blockIdx.x;
  int n = threadIdx.x;  // 64 threads
  const float* row = state + (size_t)(b*NN + n) * DD;
  float s5 = row[5], s6 = row[6];
  float d = (s5 != 0.0f && s6 != 0.0f) ? sqrtf(s5*s5 + s6*s6)
                                       : __int_as_float(0x7f800000);  // +inf

  __shared__ float ds[NN];
  ds[n] = d;
  __syncthreads();

  int rank = 0;
  #pragma unroll
  for (int j = 0; j < NN; j++){
    float dj = ds[j];
    // stable descending by d (== argsort(-d) ascending, stable)
    rank += (int)((dj > d) || (dj == d && j < n));
  }

  float* dst = g_xs + (size_t)(b*NN + rank) * 8;
  #pragma unroll
  for (int k = 0; k < II; k++) dst[k] = row[SSS + k];
  dst[7] = 0.0f;
}

// ---------------- persistent LSTM + fused MLP head ----------------
// 256 threads = 64 col-threads (4 hidden cols each) x 4 row-threads (4 rows each).
__global__ void __launch_bounds__(NTHREADS, 1)
lstm_mlp_kernel(const float* __restrict__ state,
                const float* __restrict__ W1, const float* __restrict__ b1,
                const float* __restrict__ W2, const float* __restrict__ b2,
                const float* __restrict__ Wv, const float* __restrict__ bv,
                float* __restrict__ out){
  extern __shared__ float smem[];
  float* x_sh     = smem;                      // TB*64*8   = 8192
  float* h_sh     = x_sh + TB*NN*8;            // TB*256    = 4096
  float* joint_sh = h_sh + TB*HH;              // TB*264    = 4224
  float* o1_sh    = joint_sh + TB*JP;          // TB*512    = 8192
  float* o2_sh    = o1_sh + TB*MM1;            // TB*512    = 8192

  int tid = threadIdx.x;
  int c   = tid & 63;          // col-thread: hidden cols 4c..4c+3
  int rt  = tid >> 6;          // row-thread: rows rt*4..rt*4+3
  int rowbase = rt * 4;
  int tile = blockIdx.x;
  int b0 = tile * TB;

  // load x tile (contiguous) into shared
  {
    const float4* src = (const float4*)(g_xs + (size_t)b0 * NN * 8);
    float4* dst = (float4*)x_sh;
    for (int i = tid; i < TB*NN*2; i += NTHREADS) dst[i] = src[i];
  }
  // zero h
  for (int i = tid; i < TB*HH; i += NTHREADS) h_sh[i] = 0.0f;

  // packed biases for my 4 gate-strips
  const ulonglong2* bs2 = (const ulonglong2*)g_bsum;
  ulonglong2 bb[4];
  #pragma unroll
  for (int g = 0; g < 4; g++) bb[g] = bs2[g*64 + c];

  float cst[4][4];  // cell state: [row][col], lives in registers across steps
  #pragma unroll
  for (int r = 0; r < 4; r++)
    #pragma unroll
    for (int q = 0; q < 4; q++) cst[r][q] = 0.0f;

  __syncthreads();

  const ulonglong2* WT2  = (const ulonglong2*)g_WhhT;
  const ulonglong2* WiT2 = (const ulonglong2*)g_WihT;

  // ---------------- 64 LSTM steps ----------------
  for (int t = 0; t < NN; t++){
    // acc[row][gate][pair] packed fp32x2, init with biases
    unsigned long long acc[4][4][2];
    #pragma unroll
    for (int r = 0; r < 4; r++)
      #pragma unroll
      for (int g = 0; g < 4; g++){ acc[r][g][0] = bb[g].x; acc[r][g][1] = bb[g].y; }

    // input part: k = 0..6
    #pragma unroll
    for (int k = 0; k < II; k++){
      ulonglong2 w[4];
      #pragma unroll
      for (int g = 0; g < 4; g++) w[g] = WiT2[k*256 + g*64 + c];
      #pragma unroll
      for (int r = 0; r < 4; r++){
        float xv = x_sh[(rowbase + r)*NN*8 + t*8 + k];
        unsigned long long xp = packf2(xv, xv);
        #pragma unroll
        for (int g = 0; g < 4; g++){
          acc[r][g][0] = fma2(w[g].x, xp, acc[r][g][0]);
          acc[r][g][1] = fma2(w[g].y, xp, acc[r][g][1]);
        }
      }
    }

    // recurrent part: k = 0..255
    #pragma unroll 4
    for (int k = 0; k < HH; k++){
      ulonglong2 w[4];
      #pragma unroll
      for (int g = 0; g < 4; g++) w[g] = WT2[k*256 + g*64 + c];
      #pragma unroll
      for (int r = 0; r < 4; r++){
        float hv = h_sh[(rowbase + r)*HH + k];
        unsigned long long hp = packf2(hv, hv);
        #pragma unroll
        for (int g = 0; g < 4; g++){
          acc[r][g][0] = fma2(w[g].x, hp, acc[r][g][0]);
          acc[r][g][1] = fma2(w[g].y, hp, acc[r][g][1]);
        }
      }
    }

    __syncthreads();  // all reads of h_old complete

    // cell update + write new h
    #pragma unroll
    for (int r = 0; r < 4; r++){
      float gi[4], gf[4], gg[4], go[4];
      unpackf2(acc[r][0][0], gi[0], gi[1]); unpackf2(acc[r][0][1], gi[2], gi[3]);
      unpackf2(acc[r][1][0], gf[0], gf[1]); unpackf2(acc[r][1][1], gf[2], gf[3]);
      unpackf2(acc[r][2][0], gg[0], gg[1]); unpackf2(acc[r][2][1], gg[2], gg[3]);
      unpackf2(acc[r][3][0], go[0], go[1]); unpackf2(acc[r][3][1], go[2], go[3]);
      float4 hout;
      float* hp4 = (float*)&hout;
      #pragma unroll
      for (int q = 0; q < 4; q++){
        float ii = sigf(gi[q]);
        float ff = sigf(gf[q]);
        float gv = tanh_fast(gg[q]);
        float oo = sigf(go[q]);
        float cn = ff*cst[r][q] + ii*gv;
        cst[r][q] = cn;
        hp4[q] = oo * tanh_fast(cn);
      }
      *(float4*)(h_sh + (rowbase + r)*HH + c*4) = hout;
    }
    __syncthreads();  // h_new visible before next step's reads
  }

  // ---------------- fused MLP head ----------------
  // build joint = [self_state(5), hn(256)]
  for (int idx = tid; idx < TB*(SSS+HH); idx += NTHREADS){
    int row = idx / (SSS+HH);
    int k   = idx - row*(SSS+HH);
    float v;
    if (k < SSS) v = state[(size_t)(b0 + row)*NN*DD + k];   // state[b][0][k]
    else         v = h_sh[row*HH + (k - SSS)];
    joint_sh[row*JP + k] = v;
  }
  __syncthreads();

  // layer 1: (TB x 261) @ (261 x 512) + b1, relu
  {
    int ct = tid & 127;          // cols 4ct..4ct+3
    int rb = (tid >> 7) * 8;     // 8 rows
    const ulonglong2* Wp = (const ulonglong2*)W1;
    ulonglong2 bias = ((const ulonglong2*)b1)[ct];
    unsigned long long acc1[8][2];
    #pragma unroll
    for (int r = 0; r < 8; r++){ acc1[r][0] = bias.x; acc1[r][1] = bias.y; }
    for (int k = 0; k < SSS+HH; k++){
      ulonglong2 w = Wp[k*128 + ct];
      #pragma unroll
      for (int r = 0; r < 8; r++){
        float av = joint_sh[(rb + r)*JP + k];
        unsigned long long ap = packf2(av, av);
        acc1[r][0] = fma2(w.x, ap, acc1[r][0]);
        acc1[r][1] = fma2(w.y, ap, acc1[r][1]);
      }
    }
    #pragma unroll
    for (int r = 0; r < 8; r++){
      float4 o;
      unpackf2(acc1[r][0], o.x, o.y);
      unpackf2(acc1[r][1], o.z, o.w);
      o.x = fmaxf(o.x, 0.0f); o.y = fmaxf(o.y, 0.0f);
      o.z = fmaxf(o.z, 0.0f); o.w = fmaxf(o.w, 0.0f);
      *(float4*)(o1_sh + (rb + r)*MM1 + ct*4) = o;
    }
  }
  __syncthreads();

  // layer 2: (TB x 512) @ (512 x 512) + b2, relu
  {
    int ct = tid & 127;
    int rb = (tid >> 7) * 8;
    const ulonglong2* Wp = (const ulonglong2*)W2;
    ulonglong2 bias = ((const ulonglong2*)b2)[ct];
    unsigned long long acc1[8][2];
    #pragma unroll
    for (int r = 0; r < 8; r++){ acc1[r][0] = bias.x; acc1[r][1] = bias.y; }
    for (int k = 0; k < MM1; k++){
      ulonglong2 w = Wp[k*128 + ct];
      #pragma unroll
      for (int r = 0; r < 8; r++){
        float av = o1_sh[(rb + r)*MM1 + k];
        unsigned long long ap = packf2(av, av);
        acc1[r][0] = fma2(w.x, ap, acc1[r][0]);
        acc1[r][1] = fma2(w.y, ap, acc1[r][1]);
      }
    }
    #pragma unroll
    for (int r = 0; r < 8; r++){
      float4 o;
      unpackf2(acc1[r][0], o.x, o.y);
      unpackf2(acc1[r][1], o.z, o.w);
      o.x = fmaxf(o.x, 0.0f); o.y = fmaxf(o.y, 0.0f);
      o.z = fmaxf(o.z, 0.0f); o.w = fmaxf(o.w, 0.0f);
      *(float4*)(o2_sh + (rb + r)*MM2 + ct*4) = o;
    }
  }
  __syncthreads();

  // layer 3: (TB x 512) @ (512 x 81) + bv -> out
  for (int idx = tid; idx < TB*AA; idx += NTHREADS){
    int row = idx / AA;
    int col = idx - row*AA;
    float acc = bv[col];
    const float* act = o2_sh + row*MM2;
    #pragma unroll 4
    for (int k = 0; k < MM2; k++){
      acc = fmaf(act[k], Wv[k*AA + col], acc);
    }
    out[(size_t)(b0 + row)*AA + col] = acc;
  }
}

// ---------------- launch ----------------
#define SMEM_BYTES ((TB*NN*8 + TB*HH + TB*JP + TB*MM1 + TB*MM2) * sizeof(float))

extern "C" void kernel_launch(void* const* d_in, const int* in_sizes, int n_in,
                              void* d_out, int out_size){
  (void)in_sizes; (void)n_in; (void)out_size;
  const float* state = (const float*)d_in[0];
  const float* W_ih  = (const float*)d_in[1];
  const float* W_hh  = (const float*)d_in[2];
  const float* b_ih  = (const float*)d_in[3];
  const float* b_hh  = (const float*)d_in[4];
  const float* W1    = (const float*)d_in[5];
  const float* b1    = (const float*)d_in[6];
  const float* W2    = (const float*)d_in[7];
  const float* b2    = (const float*)d_in[8];
  const float* Wv    = (const float*)d_in[9];
  const float* bv    = (const float*)d_in[10];
  float* out = (float*)d_out;

  cudaFuncSetAttribute(lstm_mlp_kernel,
                       cudaFuncAttributeMaxDynamicSharedMemorySize, (int)SMEM_BYTES);

  prep_kernel<<<256, 256>>>(W_ih, W_hh, b_ih, b_hh);
  sort_gather_kernel<<<BB, NN>>>(state);
  lstm_mlp_kernel<<<NTILES, NTHREADS, SMEM_BYTES>>>(state, W1, b1, W2, b2, Wv, bv, out);
}

// round 3
// speedup vs baseline: 1.0031x; 1.0031x over previous
#include <cuda_runtime.h>
#include <math.h>

// Problem constants
#define BB   4096
#define NN   64
#define DD   12
#define SSS  5
#define II   7
#define HH   256
#define G4   1024      // 4*H
#define MM1  512
#define MM2  512
#define AA   81

#define TB        16           // batch rows per block (LSTM kernel)
#define NTILES    (BB/TB)      // 256 blocks
#define NTHREADS  256
#define JP        264          // padded joint stride (261 -> 264)

// ---------------- device scratch (static, no allocation) ----------------
static __device__ __align__(16) float g_xs[BB*NN*8];      // sorted features, padded to 8
static __device__ __align__(16) float g_WihT[II*G4];      // [k][j] transposed W_ih
static __device__ __align__(16) float g_WhhT[HH*G4];      // [k][j] transposed W_hh
static __device__ __align__(16) float g_bsum[G4];         // b_ih + b_hh

// ---------------- packed fp32x2 helpers (Blackwell) ----------------
__device__ __forceinline__ unsigned long long packf2(float lo, float hi){
  unsigned long long r;
  asm("mov.b64 %0, {%1, %2};" : "=l"(r) : "f"(lo), "f"(hi));
  return r;
}
__device__ __forceinline__ void unpackf2(unsigned long long v, float& lo, float& hi){
  asm("mov.b64 {%0, %1}, %2;" : "=f"(lo), "=f"(hi) : "l"(v));
}
__device__ __forceinline__ unsigned long long fma2(unsigned long long a, unsigned long long b, unsigned long long c){
  unsigned long long d;
  asm("fma.rn.f32x2 %0, %1, %2, %3;" : "=l"(d) : "l"(a), "l"(b), "l"(c));
  return d;
}

__device__ __forceinline__ float sigf(float x){
  return 1.0f / (1.0f + __expf(-x));
}
__device__ __forceinline__ float tanh_fast(float x){
  float ax = fabsf(x);
  float e  = __expf(-2.0f * ax);
  float t  = (1.0f - e) / (1.0f + e);
  return copysignf(t, x);
}

// ---------------- prep: transpose weights, sum biases ----------------
__global__ void prep_kernel(const float* __restrict__ Wih, const float* __restrict__ Whh,
                            const float* __restrict__ bih, const float* __restrict__ bhh){
  int idx = blockIdx.x * blockDim.x + threadIdx.x;
  int stride = gridDim.x * blockDim.x;
  for (int o = idx; o < HH*G4; o += stride){
    int k = o >> 10, j = o & 1023;
    g_WhhT[o] = Whh[j*HH + k];
  }
  for (int o = idx; o < II*G4; o += stride){
    int k = o >> 10, j = o & 1023;
    g_WihT[o] = Wih[j*II + k];
  }
  for (int o = idx; o < G4; o += stride){
    g_bsum[o] = bih[o] + bhh[o];
  }
}

// ---------------- sort by distance (desc, stable) + gather features ----------------
__global__ void sort_gather_kernel(const float* __restrict__ state){
  int b = blockIdx.x;
  int n = threadIdx.x;  // 64 threads
  const float* row = state + (size_t)(b*NN + n) * DD;
  float s5 = row[5], s6 = row[6];
  float d = (s5 != 0.0f && s6 != 0.0f) ? sqrtf(s5*s5 + s6*s6)
                                       : __int_as_float(0x7f800000);  // +inf

  __shared__ float ds[NN];
  ds[n] = d;
  __syncthreads();

  int rank = 0;
  #pragma unroll
  for (int j = 0; j < NN; j++){
    float dj = ds[j];
    // stable descending by d (== argsort(-d) ascending, stable)
    rank += (int)((dj > d) || (dj == d && j < n));
  }

  float* dst = g_xs + (size_t)(b*NN + rank) * 8;
  #pragma unroll
  for (int k = 0; k < II; k++) dst[k] = row[SSS + k];
  dst[7] = 0.0f;
}

// ---------------- persistent LSTM + fused MLP head ----------------
// 256 threads = 64 col-threads (4 hidden cols each) x 4 row-threads (4 rows each).
__global__ void __launch_bounds__(NTHREADS, 1)
lstm_mlp_kernel(const float* __restrict__ state,
                const float* __restrict__ W1, const float* __restrict__ b1,
                const float* __restrict__ W2, const float* __restrict__ b2,
                const float* __restrict__ Wv, const float* __restrict__ bv,
                float* __restrict__ out){
  extern __shared__ float smem[];
  float* x_sh     = smem;                      // TB*64*8   = 8192
  float* h_sh     = x_sh + TB*NN*8;            // TB*256    = 4096
  float* joint_sh = h_sh + TB*HH;              // TB*264    = 4224
  float* o1_sh    = joint_sh + TB*JP;          // TB*512    = 8192
  float* o2_sh    = o1_sh + TB*MM1;            // TB*512    = 8192

  int tid = threadIdx.x;
  int c   = tid & 63;          // col-thread: hidden cols 4c..4c+3
  int rt  = tid >> 6;          // row-thread: rows rt*4..rt*4+3
  int rowbase = rt * 4;
  int tile = blockIdx.x;
  int b0 = tile * TB;

  // load x tile (contiguous) into shared
  {
    const float4* src = (const float4*)(g_xs + (size_t)b0 * NN * 8);
    float4* dst = (float4*)x_sh;
    for (int i = tid; i < TB*NN*2; i += NTHREADS) dst[i] = src[i];
  }
  // zero h
  for (int i = tid; i < TB*HH; i += NTHREADS) h_sh[i] = 0.0f;

  // packed biases for my 4 gate-strips
  const ulonglong2* bs2 = (const ulonglong2*)g_bsum;
  ulonglong2 bb[4];
  #pragma unroll
  for (int g = 0; g < 4; g++) bb[g] = bs2[g*64 + c];

  float cst[4][4];  // cell state: [row][col], lives in registers across steps
  #pragma unroll
  for (int r = 0; r < 4; r++)
    #pragma unroll
    for (int q = 0; q < 4; q++) cst[r][q] = 0.0f;

  __syncthreads();

  const ulonglong2* WT2  = (const ulonglong2*)g_WhhT;
  const ulonglong2* WiT2 = (const ulonglong2*)g_WihT;

  // ---------------- 64 LSTM steps ----------------
  for (int t = 0; t < NN; t++){
    // acc[row][gate][pair] packed fp32x2, init with biases
    unsigned long long acc[4][4][2];
    #pragma unroll
    for (int r = 0; r < 4; r++)
      #pragma unroll
      for (int g = 0; g < 4; g++){ acc[r][g][0] = bb[g].x; acc[r][g][1] = bb[g].y; }

    // input part: k = 0..6
    #pragma unroll
    for (int k = 0; k < II; k++){
      ulonglong2 w[4];
      #pragma unroll
      for (int g = 0; g < 4; g++) w[g] = WiT2[k*256 + g*64 + c];
      #pragma unroll
      for (int r = 0; r < 4; r++){
        float xv = x_sh[(rowbase + r)*NN*8 + t*8 + k];
        unsigned long long xp = packf2(xv, xv);
        #pragma unroll
        for (int g = 0; g < 4; g++){
          acc[r][g][0] = fma2(w[g].x, xp, acc[r][g][0]);
          acc[r][g][1] = fma2(w[g].y, xp, acc[r][g][1]);
        }
      }
    }

    // recurrent part: k = 0..255
    #pragma unroll 4
    for (int k = 0; k < HH; k++){
      ulonglong2 w[4];
      #pragma unroll
      for (int g = 0; g < 4; g++) w[g] = WT2[k*256 + g*64 + c];
      #pragma unroll
      for (int r = 0; r < 4; r++){
        float hv = h_sh[(rowbase + r)*HH + k];
        unsigned long long hp = packf2(hv, hv);
        #pragma unroll
        for (int g = 0; g < 4; g++){
          acc[r][g][0] = fma2(w[g].x, hp, acc[r][g][0]);
          acc[r][g][1] = fma2(w[g].y, hp, acc[r][g][1]);
        }
      }
    }

    __syncthreads();  // all reads of h_old complete

    // cell update + write new h
    #pragma unroll
    for (int r = 0; r < 4; r++){
      float gi[4], gf[4], gg[4], go[4];
      unpackf2(acc[r][0][0], gi[0], gi[1]); unpackf2(acc[r][0][1], gi[2], gi[3]);
      unpackf2(acc[r][1][0], gf[0], gf[1]); unpackf2(acc[r][1][1], gf[2], gf[3]);
      unpackf2(acc[r][2][0], gg[0], gg[1]); unpackf2(acc[r][2][1], gg[2], gg[3]);
      unpackf2(acc[r][3][0], go[0], go[1]); unpackf2(acc[r][3][1], go[2], go[3]);
      float4 hout;
      float* hp4 = (float*)&hout;
      #pragma unroll
      for (int q = 0; q < 4; q++){
        float ii = sigf(gi[q]);
        float ff = sigf(gf[q]);
        float gv = tanh_fast(gg[q]);
        float oo = sigf(go[q]);
        float cn = ff*cst[r][q] + ii*gv;
        cst[r][q] = cn;
        hp4[q] = oo * tanh_fast(cn);
      }
      *(float4*)(h_sh + (rowbase + r)*HH + c*4) = hout;
    }
    __syncthreads();  // h_new visible before next step's reads
  }

  // ---------------- fused MLP head ----------------
  // build joint = [self_state(5), hn(256)]
  for (int idx = tid; idx < TB*(SSS+HH); idx += NTHREADS){
    int row = idx / (SSS+HH);
    int k   = idx - row*(SSS+HH);
    float v;
    if (k < SSS) v = state[(size_t)(b0 + row)*NN*DD + k];   // state[b][0][k]
    else         v = h_sh[row*HH + (k - SSS)];
    joint_sh[row*JP + k] = v;
  }
  __syncthreads();

  // layer 1: (TB x 261) @ (261 x 512) + b1, relu
  {
    int ct = tid & 127;          // cols 4ct..4ct+3
    int rb = (tid >> 7) * 8;     // 8 rows
    const ulonglong2* Wp = (const ulonglong2*)W1;
    ulonglong2 bias = ((const ulonglong2*)b1)[ct];
    unsigned long long acc1[8][2];
    #pragma unroll
    for (int r = 0; r < 8; r++){ acc1[r][0] = bias.x; acc1[r][1] = bias.y; }
    for (int k = 0; k < SSS+HH; k++){
      ulonglong2 w = Wp[k*128 + ct];
      #pragma unroll
      for (int r = 0; r < 8; r++){
        float av = joint_sh[(rb + r)*JP + k];
        unsigned long long ap = packf2(av, av);
        acc1[r][0] = fma2(w.x, ap, acc1[r][0]);
        acc1[r][1] = fma2(w.y, ap, acc1[r][1]);
      }
    }
    #pragma unroll
    for (int r = 0; r < 8; r++){
      float4 o;
      unpackf2(acc1[r][0], o.x, o.y);
      unpackf2(acc1[r][1], o.z, o.w);
      o.x = fmaxf(o.x, 0.0f); o.y = fmaxf(o.y, 0.0f);
      o.z = fmaxf(o.z, 0.0f); o.w = fmaxf(o.w, 0.0f);
      *(float4*)(o1_sh + (rb + r)*MM1 + ct*4) = o;
    }
  }
  __syncthreads();

  // layer 2: (TB x 512) @ (512 x 512) + b2, relu
  {
    int ct = tid & 127;
    int rb = (tid >> 7) * 8;
    const ulonglong2* Wp = (const ulonglong2*)W2;
    ulonglong2 bias = ((const ulonglong2*)b2)[ct];
    unsigned long long acc1[8][2];
    #pragma unroll
    for (int r = 0; r < 8; r++){ acc1[r][0] = bias.x; acc1[r][1] = bias.y; }
    for (int k = 0; k < MM1; k++){
      ulonglong2 w = Wp[k*128 + ct];
      #pragma unroll
      for (int r = 0; r < 8; r++){
        float av = o1_sh[(rb + r)*MM1 + k];
        unsigned long long ap = packf2(av, av);
        acc1[r][0] = fma2(w.x, ap, acc1[r][0]);
        acc1[r][1] = fma2(w.y, ap, acc1[r][1]);
      }
    }
    #pragma unroll
    for (int r = 0; r < 8; r++){
      float4 o;
      unpackf2(acc1[r][0], o.x, o.y);
      unpackf2(acc1[r][1], o.z, o.w);
      o.x = fmaxf(o.x, 0.0f); o.y = fmaxf(o.y, 0.0f);
      o.z = fmaxf(o.z, 0.0f); o.w = fmaxf(o.w, 0.0f);
      *(float4*)(o2_sh + (rb + r)*MM2 + ct*4) = o;
    }
  }
  __syncthreads();

  // layer 3: (TB x 512) @ (512 x 81) + bv -> out
  for (int idx = tid; idx < TB*AA; idx += NTHREADS){
    int row = idx / AA;
    int col = idx - row*AA;
    float acc = bv[col];
    const float* act = o2_sh + row*MM2;
    #pragma unroll 4
    for (int k = 0; k < MM2; k++){
      acc = fmaf(act[k], Wv[k*AA + col], acc);
    }
    out[(size_t)(b0 + row)*AA + col] = acc;
  }
}

// ---------------- launch ----------------
#define SMEM_BYTES ((TB*NN*8 + TB*HH + TB*JP + TB*MM1 + TB*MM2) * sizeof(float))

extern "C" void kernel_launch(void* const* d_in, const int* in_sizes, int n_in,
                              void* d_out, int out_size){
  (void)in_sizes; (void)n_in; (void)out_size;
  const float* state = (const float*)d_in[0];
  const float* W_ih  = (const float*)d_in[1];
  const float* W_hh  = (const float*)d_in[2];
  const float* b_ih  = (const float*)d_in[3];
  const float* b_hh  = (const float*)d_in[4];
  const float* W1    = (const float*)d_in[5];
  const float* b1    = (const float*)d_in[6];
  const float* W2    = (const float*)d_in[7];
  const float* b2    = (const float*)d_in[8];
  const float* Wv    = (const float*)d_in[9];
  const float* bv    = (const float*)d_in[10];
  float* out = (float*)d_out;

  cudaFuncSetAttribute(lstm_mlp_kernel,
                       cudaFuncAttributeMaxDynamicSharedMemorySize, (int)SMEM_BYTES);

  prep_kernel<<<256, 256>>>(W_ih, W_hh, b_ih, b_hh);
  sort_gather_kernel<<<BB, NN>>>(state);
  lstm_mlp_kernel<<<NTILES, NTHREADS, SMEM_BYTES>>>(state, W1, b1, W2, b2, Wv, bv, out);
}

// round 7
// speedup vs baseline: 4.8453x; 4.8305x over previous
#include <cuda_runtime.h>
#include <cuda_fp16.h>
#include <cstdint>
#include <math.h>

#define BB  4096
#define NN  64
#define SSS 5
#define AA  81
#define JP  264

// smem byte offsets (dynamic)
#define SM_BH    0         // 256x512B  W_hh fp16 swizzled      (131072)
#define SM_AH    131072    // 128x512B  h fp16 swizzled         (65536)
#define SM_AX    196608    // 128x32B   x fp16                  (4096)
#define SM_BX    200704    // 256x32B   W_ih fp16               (8192)
#define SM_BIAS  208896    // 256 f32                           (1024)
#define SM_STAGE 209920    // 128x128B  h staging               (16384)
#define SMEM_TOT 226304
// head overlays (post-loop)
#define SM_JOINT 0
#define SM_O2    36864
#define SM_O1    131072

static __device__ __align__(16) float  g_xs[BB*NN*8];
static __device__ __align__(16) __half g_Whh16[4*256*256];

// ---------------- helpers ----------------
__device__ __forceinline__ uint32_t smem_u32(const void* p){
  uint32_t a; asm("{ .reg .u64 t; cvta.to.shared.u64 t, %1; cvt.u32.u64 %0, t; }" : "=r"(a) : "l"(p)); return a;
}
__device__ __forceinline__ uint32_t ctarank(){
  uint32_t r; asm("mov.u32 %0, %%cluster_ctarank;" : "=r"(r)); return r;
}
__device__ __forceinline__ uint32_t mapa_u32(uint32_t a, uint32_t rank){
  uint32_t r; asm("mapa.shared::cluster.u32 %0, %1, %2;" : "=r"(r) : "r"(a), "r"(rank)); return r;
}
__device__ __forceinline__ void st_cluster_v4(uint32_t a, uint4 v){
  asm volatile("st.shared::cluster.v4.b32 [%0], {%1,%2,%3,%4};"
               :: "r"(a), "r"(v.x), "r"(v.y), "r"(v.z), "r"(v.w) : "memory");
}
#define CLUSTER_SYNC() do { asm volatile("barrier.cluster.arrive.aligned;" ::: "memory"); \
                            asm volatile("barrier.cluster.wait.aligned;" ::: "memory"); } while(0)

__device__ __forceinline__ void ldm4(uint32_t* r, uint32_t addr){
  asm volatile("ldmatrix.sync.aligned.m8n8.x4.shared.b16 {%0,%1,%2,%3}, [%4];"
    : "=r"(r[0]), "=r"(r[1]), "=r"(r[2]), "=r"(r[3]) : "r"(addr));
}
__device__ __forceinline__ void mma16816(float* d, const uint32_t* a, uint32_t b0, uint32_t b1){
  asm volatile("mma.sync.aligned.m16n8k16.row.col.f32.f16.f16.f32 "
    "{%0,%1,%2,%3}, {%4,%5,%6,%7}, {%8,%9}, {%0,%1,%2,%3};"
    : "+f"(d[0]), "+f"(d[1]), "+f"(d[2]), "+f"(d[3])
    : "r"(a[0]), "r"(a[1]), "r"(a[2]), "r"(a[3]), "r"(b0), "r"(b1));
}
__device__ __forceinline__ float tanha(float x){
  float r; asm("tanh.approx.f32 %0, %1;" : "=f"(r) : "f"(x)); return r;
}
__device__ __forceinline__ float siga(float x){ return fmaf(tanha(x*0.5f), 0.5f, 0.5f); }

__device__ __forceinline__ unsigned long long packf2(float lo, float hi){
  unsigned long long r; asm("mov.b64 %0, {%1, %2};" : "=l"(r) : "f"(lo), "f"(hi)); return r;
}
__device__ __forceinline__ void unpackf2(unsigned long long v, float& lo, float& hi){
  asm("mov.b64 {%0, %1}, %2;" : "=f"(lo), "=f"(hi) : "l"(v));
}
__device__ __forceinline__ unsigned long long fma2(unsigned long long a, unsigned long long b, unsigned long long c){
  unsigned long long d; asm("fma.rn.f32x2 %0, %1, %2, %3;" : "=l"(d) : "l"(a), "l"(b), "l"(c)); return d;
}

// ---- prep: W_hh -> fp16, per-slice layout [p][n=4j+g][k] ----
__global__ void prep16(const float* __restrict__ Whh){
  int i = blockIdx.x*blockDim.x + threadIdx.x;
  if (i >= 4*256*256) return;
  int p = i>>16, n = (i>>8)&255, k = i&255;
  int j = n>>2, g = n&3;
  g_Whh16[i] = __float2half_rn(Whh[(g*256 + p*64 + j)*256 + k]);
}

// ---- sort by distance (desc, stable), gather features ----
__global__ void sort_gather(const float* __restrict__ state){
  int b = blockIdx.x, n = threadIdx.x;
  const float* row = state + (size_t)(b*NN + n)*12;
  float s5 = row[5], s6 = row[6];
  float d = (s5 != 0.0f && s6 != 0.0f) ? sqrtf(s5*s5 + s6*s6) : __int_as_float(0x7f800000);
  __shared__ float ds[NN];
  ds[n] = d; __syncthreads();
  int rank = 0;
  #pragma unroll
  for (int j = 0; j < NN; j++){ float dj = ds[j]; rank += (int)((dj > d) || (dj == d && j < n)); }
  float* dst = g_xs + (size_t)(b*NN + rank)*8;
  #pragma unroll
  for (int k = 0; k < 7; k++) dst[k] = row[SSS + k];
  dst[7] = 0.0f;
}

// ---- main: clustered mma.sync LSTM + fused head ----
__global__ void __launch_bounds__(256,1) __cluster_dims__(4,1,1)
lstm_cluster(const float* __restrict__ state,
             const float* __restrict__ Wih, const float* __restrict__ bih,
             const float* __restrict__ bhh,
             const float* __restrict__ W1, const float* __restrict__ b1,
             const float* __restrict__ W2, const float* __restrict__ b2,
             const float* __restrict__ Wv, const float* __restrict__ bv,
             float* __restrict__ out){
  extern __shared__ __align__(128) char smem[];
  uint32_t sb = smem_u32(smem);
  int tid = threadIdx.x, w = tid>>5, lane = tid&31;
  uint32_t p = ctarank();
  int tile = blockIdx.x >> 2;

  // ---- init smem ----
  {
    uint4 z = make_uint4(0,0,0,0);
    for (int i = tid; i < (65536+4096)/16; i += 256) ((uint4*)(smem + SM_AH))[i] = z;   // A_h + A_x
    for (int i = tid; i < 8192/16;        i += 256) ((uint4*)(smem + SM_BX))[i] = z;    // B_x
    const uint32_t* src = (const uint32_t*)(g_Whh16 + (size_t)p*65536);
    for (int i = tid; i < 32768; i += 256){
      int n = i>>7, kw = i&127;
      uint32_t off = (uint32_t)(n*512 + ((kw*4) ^ ((n&7)<<4)));
      *(uint32_t*)(smem + SM_BH + off) = src[i];
    }
    for (int i = tid; i < 256; i += 256){
      int j = i>>2, g = i&3, gr = g*256 + (int)p*64 + j;
      ((float*)(smem + SM_BIAS))[i] = bih[gr] + bhh[gr];
    }
  }
  __syncthreads();
  // B_x fill (after zero) + A_x for t=0
  for (int i = tid; i < 256*7; i += 256){
    int n = i/7, kx = i - n*7;
    int gr = (n&3)*256 + (int)p*64 + (n>>2);
    *(__half*)(smem + SM_BX + n*32 + kx*2) = __float2half_rn(Wih[gr*7 + kx]);
  }
  if (tid < 128){
    const float* xp = g_xs + ((size_t)(tile*128 + tid)*64 + 0)*8;
    __align__(16) __half hx[8];
    #pragma unroll
    for (int k = 0; k < 7; k++) hx[k] = __float2half_rn(xp[k]);
    hx[7] = __float2half_rn(0.0f);
    *(uint4*)(smem + SM_AX + tid*32) = *(uint4*)hx;
  }
  __syncthreads();
  CLUSTER_SYNC();

  uint32_t peerA[4];
  #pragma unroll
  for (int q = 0; q < 4; q++) peerA[q] = mapa_u32(sb + SM_AH, q);

  // warp tiling: 2 (M) x 4 (N); warp tile M=64, N=64
  int m0 = (w>>2)*64;
  int nb = (w&3)*64;
  int q  = lane&3;
  int lr = lane>>2;
  float creg[32];
  #pragma unroll
  for (int i = 0; i < 32; i++) creg[i] = 0.0f;

  const float* bias = (const float*)(smem + SM_BIAS);

  for (int t = 0; t < NN; t++){
    float acc[4][8][4];
    #pragma unroll
    for (int a = 0; a < 4; a++)
      #pragma unroll
      for (int b = 0; b < 8; b++){ acc[a][b][0]=0.f; acc[a][b][1]=0.f; acc[a][b][2]=0.f; acc[a][b][3]=0.f; }

    // 16 regular K-chunks over h
    for (int c = 0; c < 16; c++){
      int kb = c*32;
      uint32_t afr[4][4], bfr[4][4];
      #pragma unroll
      for (int mt = 0; mt < 4; mt++){
        int row = m0 + mt*16 + (lane&15);
        uint32_t addr = sb + SM_AH + row*512 + (((uint32_t)(kb + (lane>>4)*16)) ^ ((row&7)<<4));
        ldm4(afr[mt], addr);
      }
      #pragma unroll
      for (int bt = 0; bt < 4; bt++){
        int nr = nb + bt*16 + (lane&7) + ((lane>>4)<<3);
        uint32_t addr = sb + SM_BH + nr*512 + (((uint32_t)(kb + ((lane>>3)&1)*16)) ^ ((nr&7)<<4));
        ldm4(bfr[bt], addr);
      }
      #pragma unroll
      for (int mt = 0; mt < 4; mt++)
        #pragma unroll
        for (int bt = 0; bt < 4; bt++){
          mma16816(acc[mt][bt*2+0], afr[mt], bfr[bt][0], bfr[bt][1]);
          mma16816(acc[mt][bt*2+1], afr[mt], bfr[bt][2], bfr[bt][3]);
        }
    }
    // x chunk (K chunk 16): A_x / B_x
    {
      uint32_t afr[4][4], bfr[4][4];
      #pragma unroll
      for (int mt = 0; mt < 4; mt++){
        int row = m0 + mt*16 + (lane&15);
        ldm4(afr[mt], sb + SM_AX + row*32 + (lane>>4)*16);
      }
      #pragma unroll
      for (int bt = 0; bt < 4; bt++){
        int nr = nb + bt*16 + (lane&7) + ((lane>>4)<<3);
        ldm4(bfr[bt], sb + SM_BX + nr*32 + ((lane>>3)&1)*16);
      }
      #pragma unroll
      for (int mt = 0; mt < 4; mt++)
        #pragma unroll
        for (int bt = 0; bt < 4; bt++){
          mma16816(acc[mt][bt*2+0], afr[mt], bfr[bt][0], bfr[bt][1]);
          mma16816(acc[mt][bt*2+1], afr[mt], bfr[bt][2], bfr[bt][3]);
        }
    }

    CLUSTER_SYNC();   // all A reads complete cluster-wide before h overwrite

    // epilogue: gates -> cell update -> h staging
    #pragma unroll
    for (int mt = 0; mt < 4; mt++)
      #pragma unroll
      for (int nt = 0; nt < 8; nt++){
        float c0 = acc[mt][nt][0], c1 = acc[mt][nt][1], c2 = acc[mt][nt][2], c3 = acc[mt][nt][3];
        float sa = (q&1) ? c0 : c2;
        float sv = (q&1) ? c1 : c3;
        float ra = __shfl_xor_sync(0xFFFFFFFFu, sa, 1);
        float rb = __shfl_xor_sync(0xFFFFFFFFu, sv, 1);
        float gi, gf, gg, go;
        if (q&1){ gi = ra; gf = rb; gg = c2; go = c3; }
        else    { gi = c0; gf = c1; gg = ra; go = rb; }
        int jf = (nb>>2) + nt*2 + (q>>1);
        float4 bs = *(const float4*)(bias + jf*4);
        gi += bs.x; gf += bs.y; gg += bs.z; go += bs.w;
        int s = mt*8 + nt;
        float cn = siga(gf)*creg[s] + siga(gi)*tanha(gg);
        creg[s] = cn;
        float hv = siga(go)*tanha(cn);
        int rowf = m0 + mt*16 + lr + ((q&1)<<3);
        *(__half*)(smem + SM_STAGE + rowf*128 + jf*2) = __float2half_rn(hv);
      }

    // A_x for next step (local only)
    if (t < NN-1 && tid < 128){
      const float* xp = g_xs + ((size_t)(tile*128 + tid)*64 + (t+1))*8;
      __align__(16) __half hx[8];
      #pragma unroll
      for (int k = 0; k < 7; k++) hx[k] = __float2half_rn(xp[k]);
      hx[7] = __float2half_rn(0.0f);
      *(uint4*)(smem + SM_AX + tid*32) = *(uint4*)hx;
    }
    __syncthreads();

    // distribute h slice to all 4 CTAs' A_h (swizzled)
    for (int cidx = tid; cidx < 1024; cidx += 256){
      int m = cidx>>3, jb = cidx&7;
      uint4 v = *(const uint4*)(smem + SM_STAGE + m*128 + jb*16);
      uint32_t off = (uint32_t)(m*512 + (((p<<7) + jb*16) ^ ((m&7)<<4)));
      #pragma unroll
      for (int q2 = 0; q2 < 4; q2++) st_cluster_v4(peerA[q2] + off, v);
    }
    CLUSTER_SYNC();   // writes visible everywhere before next mma
  }

  // ---------------- fused MLP head: 32 rows per CTA ----------------
  float* joint = (float*)(smem + SM_JOINT);
  float* o1    = (float*)(smem + SM_O1);
  float* o2    = (float*)(smem + SM_O2);
  for (int i = tid; i < 32*261; i += 256){
    int r = i/261, k = i - r*261;
    float v;
    if (k < SSS) v = state[(size_t)(tile*128 + (int)p*32 + r)*768 + k];
    else {
      int m = (int)p*32 + r, kk = k - SSS;
      uint32_t off = (uint32_t)(m*512 + (((uint32_t)(kk*2)) ^ ((m&7)<<4)));
      v = __half2float(*(const __half*)(smem + SM_AH + off));
    }
    joint[r*JP + k] = v;
  }
  __syncthreads();
  {
    int ct = tid & 127, rb = (tid>>7)*16;
    ulonglong2 bb = ((const ulonglong2*)b1)[ct];
    unsigned long long a1[16][2];
    #pragma unroll
    for (int r = 0; r < 16; r++){ a1[r][0] = bb.x; a1[r][1] = bb.y; }
    for (int k = 0; k < 261; k++){
      ulonglong2 wv = ((const ulonglong2*)W1)[k*128 + ct];
      #pragma unroll
      for (int r = 0; r < 16; r++){
        float av = joint[(rb + r)*JP + k];
        unsigned long long ap = packf2(av, av);
        a1[r][0] = fma2(wv.x, ap, a1[r][0]);
        a1[r][1] = fma2(wv.y, ap, a1[r][1]);
      }
    }
    __syncthreads();
    #pragma unroll
    for (int r = 0; r < 16; r++){
      float4 o; unpackf2(a1[r][0], o.x, o.y); unpackf2(a1[r][1], o.z, o.w);
      o.x = fmaxf(o.x,0.f); o.y = fmaxf(o.y,0.f); o.z = fmaxf(o.z,0.f); o.w = fmaxf(o.w,0.f);
      *(float4*)(o1 + (rb + r)*512 + ct*4) = o;
    }
  }
  __syncthreads();
  {
    int ct = tid & 127, rb = (tid>>7)*16;
    ulonglong2 bb = ((const ulonglong2*)b2)[ct];
    unsigned long long a1[16][2];
    #pragma unroll
    for (int r = 0; r < 16; r++){ a1[r][0] = bb.x; a1[r][1] = bb.y; }
    for (int k = 0; k < 512; k++){
      ulonglong2 wv = ((const ulonglong2*)W2)[k*128 + ct];
      #pragma unroll
      for (int r = 0; r < 16; r++){
        float av = o1[(rb + r)*512 + k];
        unsigned long long ap = packf2(av, av);
        a1[r][0] = fma2(wv.x, ap, a1[r][0]);
        a1[r][1] = fma2(wv.y, ap, a1[r][1]);
      }
    }
    __syncthreads();
    #pragma unroll
    for (int r = 0; r < 16; r++){
      float4 o; unpackf2(a1[r][0], o.x, o.y); unpackf2(a1[r][1], o.z, o.w);
      o.x = fmaxf(o.x,0.f); o.y = fmaxf(o.y,0.f); o.z = fmaxf(o.z,0.f); o.w = fmaxf(o.w,0.f);
      *(float4*)(o2 + (rb + r)*512 + ct*4) = o;
    }
  }
  __syncthreads();
  for (int i = tid; i < 32*AA; i += 256){
    int r = i/AA, col = i - r*AA;
    float acc = bv[col];
    const float* act = o2 + r*512;
    #pragma unroll 4
    for (int k = 0; k < 512; k++) acc = fmaf(act[k], Wv[k*AA + col], acc);
    out[(size_t)(tile*128 + (int)p*32 + r)*AA + col] = acc;
  }
}

extern "C" void kernel_launch(void* const* d_in, const int* in_sizes, int n_in,
                              void* d_out, int out_size){
  (void)in_sizes; (void)n_in; (void)out_size;
  const float* state = (const float*)d_in[0];
  const float* W_ih  = (const float*)d_in[1];
  const float* W_hh  = (const float*)d_in[2];
  const float* b_ih  = (const float*)d_in[3];
  const float* b_hh  = (const float*)d_in[4];
  const float* W1    = (const float*)d_in[5];
  const float* b1    = (const float*)d_in[6];
  const float* W2    = (const float*)d_in[7];
  const float* b2    = (const float*)d_in[8];
  const float* Wv    = (const float*)d_in[9];
  const float* bv    = (const float*)d_in[10];
  float* out = (float*)d_out;

  cudaFuncSetAttribute(lstm_cluster, cudaFuncAttributeMaxDynamicSharedMemorySize, SMEM_TOT);

  prep16<<<512, 512>>>(W_hh);
  sort_gather<<<BB, NN>>>(state);
  lstm_cluster<<<128, 256, SMEM_TOT>>>(state, W_ih, b_ih, b_hh, W1, b1, W2, b2, Wv, bv, out);
}

// round 8
// speedup vs baseline: 4.9482x; 1.0212x over previous
#include <cuda_runtime.h>
#include <cuda_fp16.h>
#include <cstdint>
#include <math.h>

#define NN  64
#define SSS 5
#define AA  81
#define JP  264

// smem byte offsets
#define SM_BH    0         // 256x512B  W_hh fp16 swizzled   (131072)
#define SM_AH    131072    // 128x512B  h fp16 swizzled      (65536)
#define SM_AX    196608    // 128x32B   x fp16               (4096)
#define SM_BX    200704    // 256x32B   W_ih fp16            (8192)
#define SM_BIAS  208896    // 256 f32                        (1024)
#define SM_STAGE 209920    // 128x128B  h staging            (16384)
#define SM_ORD   226304    // u8[32][64]                     (2048)
#define SMEM_TOT 228352
// head overlays (post-loop)
#define SM_JOINT 0
#define SM_O2    36864
#define SM_O1    131072

// ---------------- helpers ----------------
__device__ __forceinline__ uint32_t smem_u32(const void* p){
  uint32_t a; asm("{ .reg .u64 t; cvta.to.shared.u64 t, %1; cvt.u32.u64 %0, t; }" : "=r"(a) : "l"(p)); return a;
}
__device__ __forceinline__ uint32_t ctarank(){
  uint32_t r; asm("mov.u32 %0, %%cluster_ctarank;" : "=r"(r)); return r;
}
__device__ __forceinline__ uint32_t mapa_u32(uint32_t a, uint32_t rank){
  uint32_t r; asm("mapa.shared::cluster.u32 %0, %1, %2;" : "=r"(r) : "r"(a), "r"(rank)); return r;
}
__device__ __forceinline__ void st_cluster_v4(uint32_t a, uint4 v){
  asm volatile("st.shared::cluster.v4.b32 [%0], {%1,%2,%3,%4};"
               :: "r"(a), "r"(v.x), "r"(v.y), "r"(v.z), "r"(v.w) : "memory");
}
#define CLUSTER_ARRIVE() asm volatile("barrier.cluster.arrive.aligned;" ::: "memory")
#define CLUSTER_WAIT()   asm volatile("barrier.cluster.wait.aligned;" ::: "memory")
#define CLUSTER_SYNC()   do { CLUSTER_ARRIVE(); CLUSTER_WAIT(); } while(0)

__device__ __forceinline__ void ldm4(uint32_t* r, uint32_t addr){
  asm volatile("ldmatrix.sync.aligned.m8n8.x4.shared.b16 {%0,%1,%2,%3}, [%4];"
    : "=r"(r[0]), "=r"(r[1]), "=r"(r[2]), "=r"(r[3]) : "r"(addr));
}
__device__ __forceinline__ void mma16816(float* d, const uint32_t* a, uint32_t b0, uint32_t b1){
  asm volatile("mma.sync.aligned.m16n8k16.row.col.f32.f16.f16.f32 "
    "{%0,%1,%2,%3}, {%4,%5,%6,%7}, {%8,%9}, {%0,%1,%2,%3};"
    : "+f"(d[0]), "+f"(d[1]), "+f"(d[2]), "+f"(d[3])
    : "r"(a[0]), "r"(a[1]), "r"(a[2]), "r"(a[3]), "r"(b0), "r"(b1));
}
__device__ __forceinline__ float tanha(float x){
  float r; asm("tanh.approx.f32 %0, %1;" : "=f"(r) : "f"(x)); return r;
}
__device__ __forceinline__ float siga(float x){ return fmaf(tanha(x*0.5f), 0.5f, 0.5f); }

__device__ __forceinline__ unsigned long long packf2(float lo, float hi){
  unsigned long long r; asm("mov.b64 %0, {%1, %2};" : "=l"(r) : "f"(lo), "f"(hi)); return r;
}
__device__ __forceinline__ void unpackf2(unsigned long long v, float& lo, float& hi){
  asm("mov.b64 {%0, %1}, %2;" : "=f"(lo), "=f"(hi) : "l"(v));
}
__device__ __forceinline__ unsigned long long fma2(unsigned long long a, unsigned long long b, unsigned long long c){
  unsigned long long d; asm("fma.rn.f32x2 %0, %1, %2, %3;" : "=l"(d) : "l"(a), "l"(b), "l"(c)); return d;
}

// ---- single fused kernel: sort + convert + clustered mma LSTM + head ----
__global__ void __launch_bounds__(256,1) __cluster_dims__(4,1,1)
lstm_cluster(const float* __restrict__ state,
             const float* __restrict__ Wih, const float* __restrict__ Whh,
             const float* __restrict__ bih, const float* __restrict__ bhh,
             const float* __restrict__ W1, const float* __restrict__ b1,
             const float* __restrict__ W2, const float* __restrict__ b2,
             const float* __restrict__ Wv, const float* __restrict__ bv,
             float* __restrict__ out){
  extern __shared__ __align__(128) char smem[];
  uint32_t sb = smem_u32(smem);
  int tid = threadIdx.x, w = tid>>5, lane = tid&31;
  uint32_t p = ctarank();
  int tile = blockIdx.x >> 2;
  unsigned char* ord = (unsigned char*)(smem + SM_ORD);

  // ---- prologue: sort own 32 rows (ds temp in STAGE) ----
  {
    float* ds = (float*)(smem + SM_STAGE);
    for (int i = tid; i < 2048; i += 256){
      int r = i>>6, n = i&63;
      const float* row = state + ((size_t)(tile*128 + (int)p*32 + r)*64 + n)*12;
      float s5 = row[5], s6 = row[6];
      ds[i] = (s5 != 0.0f && s6 != 0.0f) ? sqrtf(s5*s5 + s6*s6) : __int_as_float(0x7f800000);
    }
    __syncthreads();
    for (int i = tid; i < 2048; i += 256){
      int r = i>>6, n = i&63;
      float d = ds[r*64 + n]; int rank = 0;
      #pragma unroll 8
      for (int j = 0; j < 64; j++){
        float dj = ds[r*64 + j];
        rank += (int)((dj > d) || (dj == d && j < n));
      }
      ord[r*64 + rank] = (unsigned char)n;
    }
    __syncthreads();
  }

  // ---- prologue: fill W_hh slice fp16 swizzled, bias, W_ih (B_x), zero A_h/A_x ----
  {
    uint4 z = make_uint4(0,0,0,0);
    for (int i = tid; i < (65536+4096)/16; i += 256) ((uint4*)(smem + SM_AH))[i] = z;
    for (int i = tid; i < 8192/16;        i += 256) ((uint4*)(smem + SM_BX))[i] = z;
    __syncthreads();
    // W_hh: n = 4j+g permutation, slice p: rows g*256 + p*64 + j
    for (int i = tid; i < 32768; i += 256){
      int n = i>>7, kw = i&127;         // kw = pair of k
      int j = n>>2, g = n&3;
      float2 v = *(const float2*)(Whh + (size_t)(g*256 + (int)p*64 + j)*256 + kw*2);
      __half2 h2 = __floats2half2_rn(v.x, v.y);
      uint32_t off = (uint32_t)(n*512 + ((kw*4) ^ ((n&7)<<4)));
      *(uint32_t*)(smem + SM_BH + off) = *(uint32_t*)&h2;
    }
    for (int i = tid; i < 256; i += 256){
      int j = i>>2, g = i&3, gr = g*256 + (int)p*64 + j;
      ((float*)(smem + SM_BIAS))[i] = bih[gr] + bhh[gr];
    }
    for (int i = tid; i < 256*7; i += 256){
      int n = i/7, kx = i - n*7;
      int gr = (n&3)*256 + (int)p*64 + (n>>2);
      *(__half*)(smem + SM_BX + n*32 + kx*2) = __float2half_rn(Wih[gr*7 + kx]);
    }
  }
  __syncthreads();

  uint32_t peerAH[4], peerAX[4];
  #pragma unroll
  for (int q2 = 0; q2 < 4; q2++){
    peerAH[q2] = mapa_u32(sb + SM_AH, q2);
    peerAX[q2] = mapa_u32(sb + SM_AX, q2);
  }

  // A_x for t=0: own 32 rows -> all peers
  if (tid < 32){
    int r = tid;
    const float* xp = state + ((size_t)(tile*128 + (int)p*32 + r)*64 + ord[r*64 + 0])*12 + SSS;
    __align__(16) __half hx[8];
    #pragma unroll
    for (int k = 0; k < 7; k++) hx[k] = __float2half_rn(xp[k]);
    hx[7] = __float2half_rn(0.0f);
    uint4 v = *(uint4*)hx;
    uint32_t off = (uint32_t)(((int)p*32 + r)*32);
    #pragma unroll
    for (int q2 = 0; q2 < 4; q2++) st_cluster_v4(peerAX[q2] + off, v);
  }
  __syncthreads();
  CLUSTER_SYNC();

  // warp tiling: 2 (M) x 4 (N)
  int m0 = (w>>2)*64;
  int nb = (w&3)*64;
  int q  = lane&3;
  int lr = lane>>2;
  float creg[32];
  #pragma unroll
  for (int i = 0; i < 32; i++) creg[i] = 0.0f;
  const float* bias = (const float*)(smem + SM_BIAS);

  for (int t = 0; t < NN; t++){
    float acc[4][8][4];
    #pragma unroll
    for (int a = 0; a < 4; a++)
      #pragma unroll
      for (int b = 0; b < 8; b++){ acc[a][b][0]=0.f; acc[a][b][1]=0.f; acc[a][b][2]=0.f; acc[a][b][3]=0.f; }

    // 16 K-chunks over h
    for (int c = 0; c < 16; c++){
      int kb = c*32;
      uint32_t afr[4][4], bfr[4][4];
      #pragma unroll
      for (int mt = 0; mt < 4; mt++){
        int row = m0 + mt*16 + (lane&15);
        ldm4(afr[mt], sb + SM_AH + row*512 + (((uint32_t)(kb + (lane>>4)*16)) ^ ((row&7)<<4)));
      }
      #pragma unroll
      for (int bt = 0; bt < 4; bt++){
        int nr = nb + bt*16 + (lane&7) + ((lane>>4)<<3);
        ldm4(bfr[bt], sb + SM_BH + nr*512 + (((uint32_t)(kb + ((lane>>3)&1)*16)) ^ ((nr&7)<<4)));
      }
      #pragma unroll
      for (int mt = 0; mt < 4; mt++)
        #pragma unroll
        for (int bt = 0; bt < 4; bt++){
          mma16816(acc[mt][bt*2+0], afr[mt], bfr[bt][0], bfr[bt][1]);
          mma16816(acc[mt][bt*2+1], afr[mt], bfr[bt][2], bfr[bt][3]);
        }
    }
    // x chunk
    {
      uint32_t afr[4][4], bfr[4][4];
      #pragma unroll
      for (int mt = 0; mt < 4; mt++){
        int row = m0 + mt*16 + (lane&15);
        ldm4(afr[mt], sb + SM_AX + row*32 + (lane>>4)*16);
      }
      #pragma unroll
      for (int bt = 0; bt < 4; bt++){
        int nr = nb + bt*16 + (lane&7) + ((lane>>4)<<3);
        ldm4(bfr[bt], sb + SM_BX + nr*32 + ((lane>>3)&1)*16);
      }
      #pragma unroll
      for (int mt = 0; mt < 4; mt++)
        #pragma unroll
        for (int bt = 0; bt < 4; bt++){
          mma16816(acc[mt][bt*2+0], afr[mt], bfr[bt][0], bfr[bt][1]);
          mma16816(acc[mt][bt*2+1], afr[mt], bfr[bt][2], bfr[bt][3]);
        }
    }

    CLUSTER_ARRIVE();   // my A reads are done; overlap barrier with epilogue

    // prefetch next x (threads 0-31), overlapped with epilogue math
    float xf[7];
    bool have = (t < NN-1) && (tid < 32);
    if (have){
      const float* xp = state + ((size_t)(tile*128 + (int)p*32 + tid)*64 + ord[tid*64 + (t+1)])*12 + SSS;
      #pragma unroll
      for (int k = 0; k < 7; k++) xf[k] = xp[k];
    }

    // epilogue: gates -> cell update -> h staging
    #pragma unroll
    for (int mt = 0; mt < 4; mt++)
      #pragma unroll
      for (int nt = 0; nt < 8; nt++){
        float c0 = acc[mt][nt][0], c1 = acc[mt][nt][1], c2 = acc[mt][nt][2], c3 = acc[mt][nt][3];
        float sa = (q&1) ? c0 : c2;
        float sv = (q&1) ? c1 : c3;
        float ra = __shfl_xor_sync(0xFFFFFFFFu, sa, 1);
        float rb = __shfl_xor_sync(0xFFFFFFFFu, sv, 1);
        float gi, gf, gg, go;
        if (q&1){ gi = ra; gf = rb; gg = c2; go = c3; }
        else    { gi = c0; gf = c1; gg = ra; go = rb; }
        int jf = (nb>>2) + nt*2 + (q>>1);
        float4 bs = *(const float4*)(bias + jf*4);
        gi += bs.x; gf += bs.y; gg += bs.z; go += bs.w;
        int s = mt*8 + nt;
        float cn = siga(gf)*creg[s] + siga(gi)*tanha(gg);
        creg[s] = cn;
        float hv = siga(go)*tanha(cn);
        int rowf = m0 + mt*16 + lr + ((q&1)<<3);
        *(__half*)(smem + SM_STAGE + rowf*128 + jf*2) = __float2half_rn(hv);
      }
    __syncthreads();    // stage complete (CTA-local)
    CLUSTER_WAIT();     // everyone's reads complete -> safe to overwrite A

    // distribute h slice + next x to all 4 CTAs
    for (int cidx = tid; cidx < 1024; cidx += 256){
      int m = cidx>>3, jb = cidx&7;
      uint4 v = *(const uint4*)(smem + SM_STAGE + m*128 + jb*16);
      uint32_t off = (uint32_t)(m*512 + (((p<<7) + jb*16) ^ ((m&7)<<4)));
      #pragma unroll
      for (int q2 = 0; q2 < 4; q2++) st_cluster_v4(peerAH[q2] + off, v);
    }
    if (have){
      __align__(16) __half hx[8];
      #pragma unroll
      for (int k = 0; k < 7; k++) hx[k] = __float2half_rn(xf[k]);
      hx[7] = __float2half_rn(0.0f);
      uint4 v = *(uint4*)hx;
      uint32_t off = (uint32_t)(((int)p*32 + tid)*32);
      #pragma unroll
      for (int q2 = 0; q2 < 4; q2++) st_cluster_v4(peerAX[q2] + off, v);
    }
    CLUSTER_ARRIVE();
    CLUSTER_WAIT();     // writes visible cluster-wide
  }

  // ---------------- fused MLP head: 32 rows per CTA ----------------
  float* joint = (float*)(smem + SM_JOINT);
  float* o1    = (float*)(smem + SM_O1);
  float* o2    = (float*)(smem + SM_O2);
  for (int i = tid; i < 32*261; i += 256){
    int r = i/261, k = i - r*261;
    float v;
    if (k < SSS) v = state[(size_t)(tile*128 + (int)p*32 + r)*768 + k];
    else {
      int m = (int)p*32 + r, kk = k - SSS;
      uint32_t off = (uint32_t)(m*512 + (((uint32_t)(kk*2)) ^ ((m&7)<<4)));
      v = __half2float(*(const __half*)(smem + SM_AH + off));
    }
    joint[r*JP + k] = v;
  }
  __syncthreads();
  {
    int ct = tid & 127, rb = (tid>>7)*16;
    ulonglong2 bb = ((const ulonglong2*)b1)[ct];
    unsigned long long a1[16][2];
    #pragma unroll
    for (int r = 0; r < 16; r++){ a1[r][0] = bb.x; a1[r][1] = bb.y; }
    for (int k = 0; k < 261; k++){
      ulonglong2 wv = ((const ulonglong2*)W1)[k*128 + ct];
      #pragma unroll
      for (int r = 0; r < 16; r++){
        float av = joint[(rb + r)*JP + k];
        unsigned long long ap = packf2(av, av);
        a1[r][0] = fma2(wv.x, ap, a1[r][0]);
        a1[r][1] = fma2(wv.y, ap, a1[r][1]);
      }
    }
    __syncthreads();
    #pragma unroll
    for (int r = 0; r < 16; r++){
      float4 o; unpackf2(a1[r][0], o.x, o.y); unpackf2(a1[r][1], o.z, o.w);
      o.x = fmaxf(o.x,0.f); o.y = fmaxf(o.y,0.f); o.z = fmaxf(o.z,0.f); o.w = fmaxf(o.w,0.f);
      *(float4*)(o1 + (rb + r)*512 + ct*4) = o;
    }
  }
  __syncthreads();
  {
    int ct = tid & 127, rb = (tid>>7)*16;
    ulonglong2 bb = ((const ulonglong2*)b2)[ct];
    unsigned long long a1[16][2];
    #pragma unroll
    for (int r = 0; r < 16; r++){ a1[r][0] = bb.x; a1[r][1] = bb.y; }
    for (int k = 0; k < 512; k++){
      ulonglong2 wv = ((const ulonglong2*)W2)[k*128 + ct];
      #pragma unroll
      for (int r = 0; r < 16; r++){
        float av = o1[(rb + r)*512 + k];
        unsigned long long ap = packf2(av, av);
        a1[r][0] = fma2(wv.x, ap, a1[r][0]);
        a1[r][1] = fma2(wv.y, ap, a1[r][1]);
      }
    }
    __syncthreads();
    #pragma unroll
    for (int r = 0; r < 16; r++){
      float4 o; unpackf2(a1[r][0], o.x, o.y); unpackf2(a1[r][1], o.z, o.w);
      o.x = fmaxf(o.x,0.f); o.y = fmaxf(o.y,0.f); o.z = fmaxf(o.z,0.f); o.w = fmaxf(o.w,0.f);
      *(float4*)(o2 + (rb + r)*512 + ct*4) = o;
    }
  }
  __syncthreads();
  for (int i = tid; i < 32*AA; i += 256){
    int r = i/AA, col = i - r*AA;
    float acc = bv[col];
    const float* act = o2 + r*512;
    #pragma unroll 4
    for (int k = 0; k < 512; k++) acc = fmaf(act[k], Wv[k*AA + col], acc);
    out[(size_t)(tile*128 + (int)p*32 + r)*AA + col] = acc;
  }
}

extern "C" void kernel_launch(void* const* d_in, const int* in_sizes, int n_in,
                              void* d_out, int out_size){
  (void)in_sizes; (void)n_in; (void)out_size;
  const float* state = (const float*)d_in[0];
  const float* W_ih  = (const float*)d_in[1];
  const float* W_hh  = (const float*)d_in[2];
  const float* b_ih  = (const float*)d_in[3];
  const float* b_hh  = (const float*)d_in[4];
  const float* W1    = (const float*)d_in[5];
  const float* b1    = (const float*)d_in[6];
  const float* W2    = (const float*)d_in[7];
  const float* b2    = (const float*)d_in[8];
  const float* Wv    = (const float*)d_in[9];
  const float* bv    = (const float*)d_in[10];
  float* out = (float*)d_out;

  cudaFuncSetAttribute(lstm_cluster, cudaFuncAttributeMaxDynamicSharedMemorySize, SMEM_TOT);

  lstm_cluster<<<128, 256, SMEM_TOT>>>(state, W_ih, W_hh, b_ih, b_hh,
                                       W1, b1, W2, b2, Wv, bv, out);
}

// round 9
// speedup vs baseline: 5.9446x; 1.2014x over previous
#include <cuda_runtime.h>
#include <cuda_fp16.h>
#include <cstdint>
#include <math.h>

#define NN  64
#define SSS 5
#define AA  81
#define JP  264
#define NT  512          // threads per CTA

// smem byte offsets
#define SM_BH    0         // 256x512B  W_hh fp16 swizzled   (131072)
#define SM_AH    131072    // 128x512B  h fp16 swizzled      (65536)
#define SM_AX    196608    // 128x32B   x fp16               (4096)
#define SM_BX    200704    // 256x32B   W_ih fp16            (8192)
#define SM_BIAS  208896    // 256 f32                        (1024)
#define SM_STAGE 209920    // 128x128B  h staging            (16384)
#define SM_ORD   226304    // u8[32][64]                     (2048)
#define SMEM_TOT 228352
// head overlays (post-loop)
#define SM_JOINT 0
#define SM_O2    36864
#define SM_O1    131072

// ---------------- helpers ----------------
__device__ __forceinline__ uint32_t smem_u32(const void* p){
  uint32_t a; asm("{ .reg .u64 t; cvta.to.shared.u64 t, %1; cvt.u32.u64 %0, t; }" : "=r"(a) : "l"(p)); return a;
}
__device__ __forceinline__ uint32_t ctarank(){
  uint32_t r; asm("mov.u32 %0, %%cluster_ctarank;" : "=r"(r)); return r;
}
__device__ __forceinline__ uint32_t mapa_u32(uint32_t a, uint32_t rank){
  uint32_t r; asm("mapa.shared::cluster.u32 %0, %1, %2;" : "=r"(r) : "r"(a), "r"(rank)); return r;
}
__device__ __forceinline__ void st_cluster_v4(uint32_t a, uint4 v){
  asm volatile("st.shared::cluster.v4.b32 [%0], {%1,%2,%3,%4};"
               :: "r"(a), "r"(v.x), "r"(v.y), "r"(v.z), "r"(v.w) : "memory");
}
#define CLUSTER_ARRIVE() asm volatile("barrier.cluster.arrive.aligned;" ::: "memory")
#define CLUSTER_WAIT()   asm volatile("barrier.cluster.wait.aligned;" ::: "memory")
#define CLUSTER_SYNC()   do { CLUSTER_ARRIVE(); CLUSTER_WAIT(); } while(0)

__device__ __forceinline__ void ldm4(uint32_t* r, uint32_t addr){
  asm volatile("ldmatrix.sync.aligned.m8n8.x4.shared.b16 {%0,%1,%2,%3}, [%4];"
    : "=r"(r[0]), "=r"(r[1]), "=r"(r[2]), "=r"(r[3]) : "r"(addr));
}
__device__ __forceinline__ void mma16816(float* d, const uint32_t* a, uint32_t b0, uint32_t b1){
  asm volatile("mma.sync.aligned.m16n8k16.row.col.f32.f16.f16.f32 "
    "{%0,%1,%2,%3}, {%4,%5,%6,%7}, {%8,%9}, {%0,%1,%2,%3};"
    : "+f"(d[0]), "+f"(d[1]), "+f"(d[2]), "+f"(d[3])
    : "r"(a[0]), "r"(a[1]), "r"(a[2]), "r"(a[3]), "r"(b0), "r"(b1));
}
__device__ __forceinline__ float tanha(float x){
  float r; asm("tanh.approx.f32 %0, %1;" : "=f"(r) : "f"(x)); return r;
}
__device__ __forceinline__ float siga(float x){ return fmaf(tanha(x*0.5f), 0.5f, 0.5f); }

__device__ __forceinline__ unsigned long long packf2(float lo, float hi){
  unsigned long long r; asm("mov.b64 %0, {%1, %2};" : "=l"(r) : "f"(lo), "f"(hi)); return r;
}
__device__ __forceinline__ void unpackf2(unsigned long long v, float& lo, float& hi){
  asm("mov.b64 {%0, %1}, %2;" : "=f"(lo), "=f"(hi) : "l"(v));
}
__device__ __forceinline__ unsigned long long fma2(unsigned long long a, unsigned long long b, unsigned long long c){
  unsigned long long d; asm("fma.rn.f32x2 %0, %1, %2, %3;" : "=l"(d) : "l"(a), "l"(b), "l"(c)); return d;
}

// ---- single fused kernel: sort + convert + clustered mma LSTM + head ----
__global__ void __launch_bounds__(NT,1) __cluster_dims__(4,1,1)
lstm_cluster(const float* __restrict__ state,
             const float* __restrict__ Wih, const float* __restrict__ Whh,
             const float* __restrict__ bih, const float* __restrict__ bhh,
             const float* __restrict__ W1, const float* __restrict__ b1,
             const float* __restrict__ W2, const float* __restrict__ b2,
             const float* __restrict__ Wv, const float* __restrict__ bv,
             float* __restrict__ out){
  extern __shared__ __align__(128) char smem[];
  uint32_t sb = smem_u32(smem);
  int tid = threadIdx.x, w = tid>>5, lane = tid&31;
  uint32_t p = ctarank();
  int tile = blockIdx.x >> 2;
  unsigned char* ord = (unsigned char*)(smem + SM_ORD);

  // ---- prologue: sort own 32 rows (ds temp in STAGE) ----
  {
    float* ds = (float*)(smem + SM_STAGE);
    for (int i = tid; i < 2048; i += NT){
      int r = i>>6, n = i&63;
      const float* row = state + ((size_t)(tile*128 + (int)p*32 + r)*64 + n)*12;
      float s5 = row[5], s6 = row[6];
      ds[i] = (s5 != 0.0f && s6 != 0.0f) ? sqrtf(s5*s5 + s6*s6) : __int_as_float(0x7f800000);
    }
    __syncthreads();
    for (int i = tid; i < 2048; i += NT){
      int r = i>>6, n = i&63;
      float d = ds[r*64 + n]; int rank = 0;
      #pragma unroll 8
      for (int j = 0; j < 64; j++){
        float dj = ds[r*64 + j];
        rank += (int)((dj > d) || (dj == d && j < n));
      }
      ord[r*64 + rank] = (unsigned char)n;
    }
    __syncthreads();
  }

  // ---- prologue: fill W_hh slice fp16 swizzled, bias, W_ih (B_x), zero A_h/A_x ----
  {
    uint4 z = make_uint4(0,0,0,0);
    for (int i = tid; i < (65536+4096)/16; i += NT) ((uint4*)(smem + SM_AH))[i] = z;
    for (int i = tid; i < 8192/16;        i += NT) ((uint4*)(smem + SM_BX))[i] = z;
    __syncthreads();
    // W_hh: n = 4j+g permutation, slice p: rows g*256 + p*64 + j
    for (int i = tid; i < 32768; i += NT){
      int n = i>>7, kw = i&127;         // kw = pair of k
      int j = n>>2, g = n&3;
      float2 v = *(const float2*)(Whh + (size_t)(g*256 + (int)p*64 + j)*256 + kw*2);
      __half2 h2 = __floats2half2_rn(v.x, v.y);
      uint32_t off = (uint32_t)(n*512 + ((kw*4) ^ ((n&7)<<4)));
      *(uint32_t*)(smem + SM_BH + off) = *(uint32_t*)&h2;
    }
    for (int i = tid; i < 256; i += NT){
      int j = i>>2, g = i&3, gr = g*256 + (int)p*64 + j;
      ((float*)(smem + SM_BIAS))[i] = bih[gr] + bhh[gr];
    }
    for (int i = tid; i < 256*7; i += NT){
      int n = i/7, kx = i - n*7;
      int gr = (n&3)*256 + (int)p*64 + (n>>2);
      *(__half*)(smem + SM_BX + n*32 + kx*2) = __float2half_rn(Wih[gr*7 + kx]);
    }
  }
  __syncthreads();

  uint32_t peerAH[4], peerAX[4];
  #pragma unroll
  for (int q2 = 0; q2 < 4; q2++){
    peerAH[q2] = mapa_u32(sb + SM_AH, q2);
    peerAX[q2] = mapa_u32(sb + SM_AX, q2);
  }

  // A_x for t=0: own 32 rows -> all peers
  if (tid < 32){
    int r = tid;
    const float* xp = state + ((size_t)(tile*128 + (int)p*32 + r)*64 + ord[r*64 + 0])*12 + SSS;
    __align__(16) __half hx[8];
    #pragma unroll
    for (int k = 0; k < 7; k++) hx[k] = __float2half_rn(xp[k]);
    hx[7] = __float2half_rn(0.0f);
    uint4 v = *(uint4*)hx;
    uint32_t off = (uint32_t)(((int)p*32 + r)*32);
    #pragma unroll
    for (int q2 = 0; q2 < 4; q2++) st_cluster_v4(peerAX[q2] + off, v);
  }
  __syncthreads();
  CLUSTER_SYNC();

  // warp tiling: 4 (M) x 4 (N); warp tile M=32, N=64
  int m0 = (w>>2)*32;
  int nb = (w&3)*64;
  int q  = lane&3;
  int lr = lane>>2;
  float creg[16];
  #pragma unroll
  for (int i = 0; i < 16; i++) creg[i] = 0.0f;
  const float* bias = (const float*)(smem + SM_BIAS);

  for (int t = 0; t < NN; t++){
    float acc[2][8][4];
    #pragma unroll
    for (int a = 0; a < 2; a++)
      #pragma unroll
      for (int b = 0; b < 8; b++){ acc[a][b][0]=0.f; acc[a][b][1]=0.f; acc[a][b][2]=0.f; acc[a][b][3]=0.f; }

    // 16 K-chunks over h
    #pragma unroll 2
    for (int c = 0; c < 16; c++){
      int kb = c*32;
      uint32_t afr[2][4], bfr[4][4];
      #pragma unroll
      for (int mt = 0; mt < 2; mt++){
        int row = m0 + mt*16 + (lane&15);
        ldm4(afr[mt], sb + SM_AH + row*512 + (((uint32_t)(kb + (lane>>4)*16)) ^ ((row&7)<<4)));
      }
      #pragma unroll
      for (int bt = 0; bt < 4; bt++){
        int nr = nb + bt*16 + (lane&7) + ((lane>>4)<<3);
        ldm4(bfr[bt], sb + SM_BH + nr*512 + (((uint32_t)(kb + ((lane>>3)&1)*16)) ^ ((nr&7)<<4)));
      }
      #pragma unroll
      for (int mt = 0; mt < 2; mt++)
        #pragma unroll
        for (int bt = 0; bt < 4; bt++){
          mma16816(acc[mt][bt*2+0], afr[mt], bfr[bt][0], bfr[bt][1]);
          mma16816(acc[mt][bt*2+1], afr[mt], bfr[bt][2], bfr[bt][3]);
        }
    }
    // x chunk
    {
      uint32_t afr[2][4], bfr[4][4];
      #pragma unroll
      for (int mt = 0; mt < 2; mt++){
        int row = m0 + mt*16 + (lane&15);
        ldm4(afr[mt], sb + SM_AX + row*32 + (lane>>4)*16);
      }
      #pragma unroll
      for (int bt = 0; bt < 4; bt++){
        int nr = nb + bt*16 + (lane&7) + ((lane>>4)<<3);
        ldm4(bfr[bt], sb + SM_BX + nr*32 + ((lane>>3)&1)*16);
      }
      #pragma unroll
      for (int mt = 0; mt < 2; mt++)
        #pragma unroll
        for (int bt = 0; bt < 4; bt++){
          mma16816(acc[mt][bt*2+0], afr[mt], bfr[bt][0], bfr[bt][1]);
          mma16816(acc[mt][bt*2+1], afr[mt], bfr[bt][2], bfr[bt][3]);
        }
    }

    CLUSTER_ARRIVE();   // my A reads are done; overlap barrier with epilogue

    // prefetch next x (threads 0-31), overlapped with epilogue math
    float xf[7];
    bool have = (t < NN-1) && (tid < 32);
    if (have){
      const float* xp = state + ((size_t)(tile*128 + (int)p*32 + tid)*64 + ord[tid*64 + (t+1)])*12 + SSS;
      #pragma unroll
      for (int k = 0; k < 7; k++) xf[k] = xp[k];
    }

    // epilogue: gates -> cell update -> h staging
    #pragma unroll
    for (int mt = 0; mt < 2; mt++)
      #pragma unroll
      for (int nt = 0; nt < 8; nt++){
        float c0 = acc[mt][nt][0], c1 = acc[mt][nt][1], c2 = acc[mt][nt][2], c3 = acc[mt][nt][3];
        float sa = (q&1) ? c0 : c2;
        float sv = (q&1) ? c1 : c3;
        float ra = __shfl_xor_sync(0xFFFFFFFFu, sa, 1);
        float rb = __shfl_xor_sync(0xFFFFFFFFu, sv, 1);
        float gi, gf, gg, go;
        if (q&1){ gi = ra; gf = rb; gg = c2; go = c3; }
        else    { gi = c0; gf = c1; gg = ra; go = rb; }
        int jf = (nb>>2) + nt*2 + (q>>1);
        float4 bs = *(const float4*)(bias + jf*4);
        gi += bs.x; gf += bs.y; gg += bs.z; go += bs.w;
        int s = mt*8 + nt;
        float cn = siga(gf)*creg[s] + siga(gi)*tanha(gg);
        creg[s] = cn;
        float hv = siga(go)*tanha(cn);
        int rowf = m0 + mt*16 + lr + ((q&1)<<3);
        *(__half*)(smem + SM_STAGE + rowf*128 + jf*2) = __float2half_rn(hv);
      }
    __syncthreads();    // stage complete (CTA-local)
    CLUSTER_WAIT();     // everyone's reads complete -> safe to overwrite A

    // distribute h slice + next x to all 4 CTAs
    for (int cidx = tid; cidx < 1024; cidx += NT){
      int m = cidx>>3, jb = cidx&7;
      uint4 v = *(const uint4*)(smem + SM_STAGE + m*128 + jb*16);
      uint32_t off = (uint32_t)(m*512 + (((p<<7) + jb*16) ^ ((m&7)<<4)));
      #pragma unroll
      for (int q2 = 0; q2 < 4; q2++) st_cluster_v4(peerAH[q2] + off, v);
    }
    if (have){
      __align__(16) __half hx[8];
      #pragma unroll
      for (int k = 0; k < 7; k++) hx[k] = __float2half_rn(xf[k]);
      hx[7] = __float2half_rn(0.0f);
      uint4 v = *(uint4*)hx;
      uint32_t off = (uint32_t)(((int)p*32 + tid)*32);
      #pragma unroll
      for (int q2 = 0; q2 < 4; q2++) st_cluster_v4(peerAX[q2] + off, v);
    }
    CLUSTER_ARRIVE();
    CLUSTER_WAIT();     // writes visible cluster-wide
  }

  // ---------------- fused MLP head: 32 rows per CTA ----------------
  float* joint = (float*)(smem + SM_JOINT);
  float* o1    = (float*)(smem + SM_O1);
  float* o2    = (float*)(smem + SM_O2);
  for (int i = tid; i < 32*261; i += NT){
    int r = i/261, k = i - r*261;
    float v;
    if (k < SSS) v = state[(size_t)(tile*128 + (int)p*32 + r)*768 + k];
    else {
      int m = (int)p*32 + r, kk = k - SSS;
      uint32_t off = (uint32_t)(m*512 + (((uint32_t)(kk*2)) ^ ((m&7)<<4)));
      v = __half2float(*(const __half*)(smem + SM_AH + off));
    }
    joint[r*JP + k] = v;
  }
  __syncthreads();
  {
    int ct = tid & 127, rb = (tid>>7)*8;   // 4 row-groups x 8 rows
    ulonglong2 bb = ((const ulonglong2*)b1)[ct];
    unsigned long long a1[8][2];
    #pragma unroll
    for (int r = 0; r < 8; r++){ a1[r][0] = bb.x; a1[r][1] = bb.y; }
    for (int k = 0; k < 261; k++){
      ulonglong2 wv = ((const ulonglong2*)W1)[k*128 + ct];
      #pragma unroll
      for (int r = 0; r < 8; r++){
        float av = joint[(rb + r)*JP + k];
        unsigned long long ap = packf2(av, av);
        a1[r][0] = fma2(wv.x, ap, a1[r][0]);
        a1[r][1] = fma2(wv.y, ap, a1[r][1]);
      }
    }
    __syncthreads();
    #pragma unroll
    for (int r = 0; r < 8; r++){
      float4 o; unpackf2(a1[r][0], o.x, o.y); unpackf2(a1[r][1], o.z, o.w);
      o.x = fmaxf(o.x,0.f); o.y = fmaxf(o.y,0.f); o.z = fmaxf(o.z,0.f); o.w = fmaxf(o.w,0.f);
      *(float4*)(o1 + (rb + r)*512 + ct*4) = o;
    }
  }
  __syncthreads();
  {
    int ct = tid & 127, rb = (tid>>7)*8;
    ulonglong2 bb = ((const ulonglong2*)b2)[ct];
    unsigned long long a1[8][2];
    #pragma unroll
    for (int r = 0; r < 8; r++){ a1[r][0] = bb.x; a1[r][1] = bb.y; }
    for (int k = 0; k < 512; k++){
      ulonglong2 wv = ((const ulonglong2*)W2)[k*128 + ct];
      #pragma unroll
      for (int r = 0; r < 8; r++){
        float av = o1[(rb + r)*512 + k];
        unsigned long long ap = packf2(av, av);
        a1[r][0] = fma2(wv.x, ap, a1[r][0]);
        a1[r][1] = fma2(wv.y, ap, a1[r][1]);
      }
    }
    __syncthreads();
    #pragma unroll
    for (int r = 0; r < 8; r++){
      float4 o; unpackf2(a1[r][0], o.x, o.y); unpackf2(a1[r][1], o.z, o.w);
      o.x = fmaxf(o.x,0.f); o.y = fmaxf(o.y,0.f); o.z = fmaxf(o.z,0.f); o.w = fmaxf(o.w,0.f);
      *(float4*)(o2 + (rb + r)*512 + ct*4) = o;
    }
  }
  __syncthreads();
  for (int i = tid; i < 32*AA; i += NT){
    int r = i/AA, col = i - r*AA;
    float acc = bv[col];
    const float* act = o2 + r*512;
    #pragma unroll 4
    for (int k = 0; k < 512; k++) acc = fmaf(act[k], Wv[k*AA + col], acc);
    out[(size_t)(tile*128 + (int)p*32 + r)*AA + col] = acc;
  }
}

extern "C" void kernel_launch(void* const* d_in, const int* in_sizes, int n_in,
                              void* d_out, int out_size){
  (void)in_sizes; (void)n_in; (void)out_size;
  const float* state = (const float*)d_in[0];
  const float* W_ih  = (const float*)d_in[1];
  const float* W_hh  = (const float*)d_in[2];
  const float* b_ih  = (const float*)d_in[3];
  const float* b_hh  = (const float*)d_in[4];
  const float* W1    = (const float*)d_in[5];
  const float* b1    = (const float*)d_in[6];
  const float* W2    = (const float*)d_in[7];
  const float* b2    = (const float*)d_in[8];
  const float* Wv    = (const float*)d_in[9];
  const float* bv    = (const float*)d_in[10];
  float* out = (float*)d_out;

  cudaFuncSetAttribute(lstm_cluster, cudaFuncAttributeMaxDynamicSharedMemorySize, SMEM_TOT);

  lstm_cluster<<<128, NT, SMEM_TOT>>>(state, W_ih, W_hh, b_ih, b_hh,
                                      W1, b1, W2, b2, Wv, bv, out);
}